// round 17
// baseline (speedup 1.0000x reference)
#include <cuda_runtime.h>
#include <cuda_bf16.h>
#include <cuda_fp16.h>

#define CC    256
#define HEADS 64
#define HD    4
#define TT    32

typedef unsigned long long u64;
typedef unsigned int u32;

__device__ __align__(16) float g_q[2785280];      // (N,C,L) per level
__device__ __align__(16) float g_k[2850816];      // (n,h,m,4) per level
__device__ __align__(16) float g_v[2850816];
__device__ __align__(16) float g_attn[2785280];
__device__ float g_pooled[4 * 2 * CC];

__constant__ int c_L[4]     = {4096, 1024, 256, 64};
__constant__ int c_kvoff[4] = {0, 2113536, 2654208, 2801664};

__device__ __forceinline__ u32 pkhf(float lo, float hi) {   // f16x2 {lo,hi}
    u32 r; asm("cvt.rn.f16x2.f32 %0, %1, %2;" : "=r"(r) : "f"(hi), "f"(lo)); return r;
}
__device__ __forceinline__ float tf32f(float x) {
    u32 r; asm("cvt.rna.tf32.f32 %0,%1;" : "=r"(r) : "f"(x));
    return __uint_as_float(r);
}
__device__ __forceinline__ u32 smem_u32(const void* p) {
    u32 a; asm("{.reg .u64 t; cvta.to.shared.u64 t, %1; cvt.u32.u64 %0, t;}" : "=r"(a) : "l"(p));
    return a;
}

// ---------------- pooled mean (also zeroes ds output) ----------------
__global__ void pooled_kernel(const float* __restrict__ d0, const float* __restrict__ d1,
                              const float* __restrict__ d2, const float* __restrict__ d3,
                              float* __restrict__ dsout) {
    __shared__ float red[256];
    int lvl = blockIdx.z, n = blockIdx.y, c = blockIdx.x;
    if (lvl == 0 && n == 0 && c == 0 && threadIdx.x < 8) dsout[threadIdx.x] = 0.f;
    const float* dp = (lvl == 0) ? d0 : (lvl == 1) ? d1 : (lvl == 2) ? d2 : d3;
    int L = c_L[lvl];
    const float* p = dp + (size_t)(n * CC + c) * L;
    float s = 0.f;
    for (int i = threadIdx.x; i < L; i += blockDim.x) s += p[i];
    red[threadIdx.x] = s;
    __syncthreads();
    for (int st = blockDim.x >> 1; st > 0; st >>= 1) {
        if (threadIdx.x < st) red[threadIdx.x] += red[threadIdx.x + st];
        __syncthreads();
    }
    if (threadIdx.x == 0) g_pooled[(lvl * 2 + n) * CC + c] = red[0] / (float)L;
}

// ---------------- ds token projections -> tail of k/v ----------------
__global__ void token_kernel(const float* __restrict__ Wdsk, const float* __restrict__ bdsk,
                             const float* __restrict__ Wdsv, const float* __restrict__ bdsv,
                             const float* __restrict__ gate) {
    int kind = blockIdx.y;
    int lvl = blockIdx.z >> 1, n = blockIdx.z & 1;
    int warp = threadIdx.x >> 5, lane = threadIdx.x & 31;
    int j = blockIdx.x * 8 + warp;
    const float* Wr = (kind ? Wdsv : Wdsk) + (size_t)(lvl * 8192 + j) * 256;
    const float* pl = g_pooled + (lvl * 2 + n) * CC;
    float s = 0.f;
#pragma unroll
    for (int c = lane; c < 256; c += 32) s += Wr[c] * pl[c];
#pragma unroll
    for (int off = 16; off > 0; off >>= 1) s += __shfl_down_sync(0xffffffffu, s, off);
    if (lane == 0) {
        s += (kind ? bdsv : bdsk)[lvl * 8192 + j];
        if (kind) s *= 1.0f / (1.0f + __expf(-gate[lvl]));
        int h = j >> 7, d = (j >> 5) & 3, t = j & 31;
        int L = c_L[lvl], M = L + TT;
        size_t idx = (size_t)c_kvoff[lvl] + ((size_t)((n * HEADS + h) * M) + (L + t)) * HD + d;
        if (kind) g_v[idx] = s; else g_k[idx] = s;
    }
}

// ---------------- shared tf32 GEMM mainloop (double-buffered) ----------------
struct GemmCoords { int wrow[2], wk[2], xrow[2], xcc[2]; };

__device__ __forceinline__ void gemm_mainloop(const float* __restrict__ W,
                                              const float* __restrict__ X,
                                              int L, int o0, int l0,
                                              float (&As)[2][16][72], float (&Bs)[2][16][72],
                                              float (&acc)[8][4],
                                              int tid, int wid, int g, int tg) {
    GemmCoords cd;
#pragma unroll
    for (int r = 0; r < 2; r++) {
        int idx = tid + r * 128;
        cd.wrow[r] = idx >> 2;  cd.wk[r]  = (idx & 3) << 2;
        cd.xrow[r] = idx >> 4;  cd.xcc[r] = (idx & 15) << 2;
    }
    float4 wr[2], xr[2];
#pragma unroll
    for (int r = 0; r < 2; r++) {
        wr[r] = *(const float4*)&W[(size_t)(o0 + cd.wrow[r]) * 256 + cd.wk[r]];
        xr[r] = *(const float4*)&X[(size_t)cd.xrow[r] * L + l0 + cd.xcc[r]];
    }
#pragma unroll
    for (int r = 0; r < 2; r++) {
        As[0][cd.wk[r]][cd.wrow[r]]     = tf32f(wr[r].x);
        As[0][cd.wk[r] + 1][cd.wrow[r]] = tf32f(wr[r].y);
        As[0][cd.wk[r] + 2][cd.wrow[r]] = tf32f(wr[r].z);
        As[0][cd.wk[r] + 3][cd.wrow[r]] = tf32f(wr[r].w);
        Bs[0][cd.xrow[r]][cd.xcc[r]]     = tf32f(xr[r].x);
        Bs[0][cd.xrow[r]][cd.xcc[r] + 1] = tf32f(xr[r].y);
        Bs[0][cd.xrow[r]][cd.xcc[r] + 2] = tf32f(xr[r].z);
        Bs[0][cd.xrow[r]][cd.xcc[r] + 3] = tf32f(xr[r].w);
    }
    __syncthreads();

    int buf = 0;
    for (int k0 = 0; k0 < 256; k0 += 16) {
        bool pf = (k0 + 16 < 256);
        if (pf) {
#pragma unroll
            for (int r = 0; r < 2; r++) {
                wr[r] = *(const float4*)&W[(size_t)(o0 + cd.wrow[r]) * 256 + k0 + 16 + cd.wk[r]];
                xr[r] = *(const float4*)&X[(size_t)(k0 + 16 + cd.xrow[r]) * L + l0 + cd.xcc[r]];
            }
        }
#pragma unroll
        for (int ks = 0; ks < 2; ks++) {
            int kb = ks * 8;
            u32 a0 = __float_as_uint(As[buf][kb + tg][wid * 16 + g]);
            u32 a1 = __float_as_uint(As[buf][kb + tg][wid * 16 + g + 8]);
            u32 a2 = __float_as_uint(As[buf][kb + tg + 4][wid * 16 + g]);
            u32 a3 = __float_as_uint(As[buf][kb + tg + 4][wid * 16 + g + 8]);
#pragma unroll
            for (int nt = 0; nt < 8; nt++) {
                u32 b0 = __float_as_uint(Bs[buf][kb + tg][nt * 8 + g]);
                u32 b1 = __float_as_uint(Bs[buf][kb + tg + 4][nt * 8 + g]);
                asm("mma.sync.aligned.m16n8k8.row.col.f32.tf32.tf32.f32 "
                    "{%0,%1,%2,%3},{%4,%5,%6,%7},{%8,%9},{%0,%1,%2,%3};"
                    : "+f"(acc[nt][0]), "+f"(acc[nt][1]), "+f"(acc[nt][2]), "+f"(acc[nt][3])
                    : "r"(a0), "r"(a1), "r"(a2), "r"(a3), "r"(b0), "r"(b1));
            }
        }
        if (pf) {
            int nb = buf ^ 1;
#pragma unroll
            for (int r = 0; r < 2; r++) {
                As[nb][cd.wk[r]][cd.wrow[r]]     = tf32f(wr[r].x);
                As[nb][cd.wk[r] + 1][cd.wrow[r]] = tf32f(wr[r].y);
                As[nb][cd.wk[r] + 2][cd.wrow[r]] = tf32f(wr[r].z);
                As[nb][cd.wk[r] + 3][cd.wrow[r]] = tf32f(wr[r].w);
                Bs[nb][cd.xrow[r]][cd.xcc[r]]     = tf32f(xr[r].x);
                Bs[nb][cd.xrow[r]][cd.xcc[r] + 1] = tf32f(xr[r].y);
                Bs[nb][cd.xrow[r]][cd.xcc[r] + 2] = tf32f(xr[r].z);
                Bs[nb][cd.xrow[r]][cd.xcc[r] + 3] = tf32f(xr[r].w);
            }
            __syncthreads();
        }
        buf ^= 1;
    }
}

// ---------------- fused q/k/v GEMM: blockIdx.y = type*4 + row-tile ----------------
__global__ void __launch_bounds__(128) gemm_qkv(const float* __restrict__ Wq,
                                                const float* __restrict__ Wk,
                                                const float* __restrict__ Wv,
                                                const float* __restrict__ bq,
                                                const float* __restrict__ bk,
                                                const float* __restrict__ bv,
                                                const float* __restrict__ sp,
                                                const float* __restrict__ iv,
                                                int L, int M, int offq, int offkv) {
    __shared__ float As[2][16][72];
    __shared__ float Bs[2][16][72];
    int n = blockIdx.z;
    int type = blockIdx.y >> 2;
    int o0 = (blockIdx.y & 3) * 64, l0 = blockIdx.x * 64;
    const float* W = (type == 0) ? Wq : (type == 1) ? Wk : Wv;
    const float* bias = (type == 0) ? bq : (type == 1) ? bk : bv;
    const float* X = ((type == 0) ? sp : iv) + (size_t)n * CC * L;
    int tid = threadIdx.x, wid = tid >> 5, lane = tid & 31;
    int g = lane >> 2, tg = lane & 3;

    float acc[8][4];
#pragma unroll
    for (int i = 0; i < 8; i++)
#pragma unroll
        for (int j = 0; j < 4; j++) acc[i][j] = 0.f;

    gemm_mainloop(W, X, L, o0, l0, As, Bs, acc, tid, wid, g, tg);

    int r0 = o0 + wid * 16 + g, r1 = r0 + 8;
    float b0v = bias[r0], b1v = bias[r1];
#pragma unroll
    for (int nt = 0; nt < 8; nt++) {
        int l = l0 + nt * 8 + 2 * tg;
        float v00 = acc[nt][0] + b0v, v01 = acc[nt][1] + b0v;
        float v10 = acc[nt][2] + b1v, v11 = acc[nt][3] + b1v;
        if (type == 0) {
            g_q[offq + (size_t)(n * CC + r0) * L + l]     = v00;
            g_q[offq + (size_t)(n * CC + r0) * L + l + 1] = v01;
            g_q[offq + (size_t)(n * CC + r1) * L + l]     = v10;
            g_q[offq + (size_t)(n * CC + r1) * L + l + 1] = v11;
        } else {
            float* dst = (type == 1) ? g_k : g_v;
            size_t i00 = (size_t)offkv + ((size_t)((n * HEADS + (r0 >> 2)) * M) + l) * HD + (r0 & 3);
            size_t i10 = (size_t)offkv + ((size_t)((n * HEADS + (r1 >> 2)) * M) + l) * HD + (r1 & 3);
            dst[i00] = v00; dst[i00 + HD] = v01;
            dst[i10] = v10; dst[i10 + HD] = v11;
        }
    }
}

// ---------------- output GEMM (+residual) ----------------
__global__ void __launch_bounds__(128) gemm_o(const float* __restrict__ W,
                                              const float* __restrict__ bias,
                                              const float* __restrict__ res,
                                              float* __restrict__ dext,
                                              int L, int off) {
    __shared__ float As[2][16][72];
    __shared__ float Bs[2][16][72];
    int n = blockIdx.z;
    int o0 = blockIdx.y * 64, l0 = blockIdx.x * 64;
    const float* X = g_attn + off + (size_t)n * CC * L;
    int tid = threadIdx.x, wid = tid >> 5, lane = tid & 31;
    int g = lane >> 2, tg = lane & 3;

    float acc[8][4];
#pragma unroll
    for (int i = 0; i < 8; i++)
#pragma unroll
        for (int j = 0; j < 4; j++) acc[i][j] = 0.f;

    gemm_mainloop(W, X, L, o0, l0, As, Bs, acc, tid, wid, g, tg);

    int r0 = o0 + wid * 16 + g, r1 = r0 + 8;
    float b0v = bias[r0], b1v = bias[r1];
#pragma unroll
    for (int nt = 0; nt < 8; nt++) {
        int l = l0 + nt * 8 + 2 * tg;
        size_t b = (size_t)(n * CC + r0) * L + l;
        size_t c = (size_t)(n * CC + r1) * L + l;
        dext[off + b]     = acc[nt][0] + b0v + res[b];
        dext[off + b + 1] = acc[nt][1] + b0v + res[b + 1];
        dext[off + c]     = acc[nt][2] + b1v + res[c];
        dext[off + c + 1] = acc[nt][3] + b1v + res[c + 1];
    }
}

// ---------------- HMMA attention: 4 q-tiles/CTA, f16-accum S-mma, k16 O-mma ---------
// Per 16-key iter: 4 LDS + 4 tiles x (2 S-mma(f16 D) + 4 ex2.f16x2 + 1 k16 O-mma).
// Four independent accumulation chains per warp keep the HMMA pipe full.
// V cols = [v0..v3, 1, ds-indicator, 0, 0] f16; den from ones column; OOB rows zero.
__global__ void __launch_bounds__(128) attn_mma(int qoff, int kvoff, int L, int M,
                                                float* __restrict__ dsout,
                                                float inv_hl, int lvl) {
    __shared__ __align__(16) uint2 s_k[2][128];   // per key: {k01, k23} f16x2
    __shared__ __align__(16) uint4 s_v[2][128];   // per pair: [c01..c31],[1,ds,0,0]
    __shared__ float s_red[4];

    int tid = threadIdx.x, wid = tid >> 5, lane = tid & 31;
    int g = lane >> 2, tg = lane & 3;
    int n = blockIdx.z, h = blockIdx.y;
    int q0 = blockIdx.x * 256 + wid * 16 + g;        // tile ti rows q0+64*ti, +8
    bool tv[4];
#pragma unroll
    for (int ti = 0; ti < 4; ti++) tv[ti] = (blockIdx.x * 256 + ti * 64) < L;

    const float SCALE = 0.5f * 1.4426950408889634f;
    size_t qbase = (size_t)qoff + ((size_t)(n * CC) + h * HD) * L;

    // Build S-mma A fragments for the 4 tiles
    u32 af0[4], af1[4];
#pragma unroll
    for (int ti = 0; ti < 4; ti++) {
        int qq = tv[ti] ? (q0 + ti * 64) : q0;
        float h0[4], l0f[4], h1[4], l1f[4];
#pragma unroll
        for (int d = 0; d < 4; d++) {
            float v = g_q[qbase + (size_t)d * L + qq] * SCALE;
            float hf = __half2float(__float2half(v));
            h0[d] = hf; l0f[d] = v - hf;
            v = g_q[qbase + (size_t)d * L + qq + 8] * SCALE;
            hf = __half2float(__float2half(v));
            h1[d] = hf; l1f[d] = v - hf;
        }
        af0[ti] = (tg == 0) ? pkhf(h0[0], h0[1]) : (tg == 1) ? pkhf(h0[2], h0[3])
                : (tg == 2) ? pkhf(l0f[0], l0f[1]) : pkhf(l0f[2], l0f[3]);
        af1[ti] = (tg == 0) ? pkhf(h1[0], h1[1]) : (tg == 1) ? pkhf(h1[2], h1[3])
                : (tg == 2) ? pkhf(l1f[0], l1f[1]) : pkhf(l1f[2], l1f[3]);
    }

    const float4* kp = (const float4*)g_k + (kvoff >> 2) + (size_t)(n * HEADS + h) * M;
    const float4* vp = (const float4*)g_v + (kvoff >> 2) + (size_t)(n * HEADS + h) * M;

    float o[4][4];
#pragma unroll
    for (int ti = 0; ti < 4; ti++)
#pragma unroll
        for (int j = 0; j < 4; j++) o[ti][j] = 0.f;

    u32 skb0 = smem_u32(s_k), svb0 = smem_u32(s_v);
    int nch = (M + 127) >> 7;
    const float4 FZ = make_float4(0.f, 0.f, 0.f, 0.f);

    // prologue: stage chunk 0
    {
        float4 kk = (tid < M) ? kp[tid] : FZ;
        s_k[0][tid] = make_uint2(pkhf(kk.x, kk.y), pkhf(kk.z, kk.w));
        if (tid < 64) {
            int m0 = 2 * tid, m1 = m0 + 1;
            float4 v0 = (m0 < M) ? vp[m0] : FZ;
            float4 v1 = (m1 < M) ? vp[m1] : FZ;
            float one0 = (m0 < M) ? 1.f : 0.f, one1 = (m1 < M) ? 1.f : 0.f;
            float dsi0 = (m0 >= L && m0 < M) ? 1.f : 0.f;
            float dsi1 = (m1 >= L && m1 < M) ? 1.f : 0.f;
            s_v[0][2 * tid]     = make_uint4(pkhf(v0.x, v1.x), pkhf(v0.y, v1.y),
                                             pkhf(v0.z, v1.z), pkhf(v0.w, v1.w));
            s_v[0][2 * tid + 1] = make_uint4(pkhf(one0, one1), pkhf(dsi0, dsi1), 0u, 0u);
        }
    }
    __syncthreads();

    int buf = 0;
    for (int t = 0; t < nch; t++) {
        bool pf = (t + 1 < nch);
        float4 kk = FZ, v0 = FZ, v1 = FZ;
        int nb_base = t * 128 + 128;
        if (pf) {
            int m = nb_base + tid;
            if (m < M) kk = kp[m];
            if (tid < 64) {
                int m0 = nb_base + 2 * tid;
                if (m0 < M)     v0 = vp[m0];
                if (m0 + 1 < M) v1 = vp[m0 + 1];
            }
        }

        u32 skb = skb0 + (u32)buf * 1024;
        u32 svb = svb0 + (u32)buf * 2048;
#pragma unroll
        for (int blk = 0; blk < 8; blk++) {      // 16 keys per iteration
            u32 k0f, k1f;
            u32 ka0 = skb + ((u32)(blk * 16 + g) << 3) + ((u32)(tg & 1) << 2);
            u32 ka1 = ka0 + (8u << 3);
            asm("ld.shared.u32 %0,[%1];" : "=r"(k0f) : "r"(ka0));
            asm("ld.shared.u32 %0,[%1];" : "=r"(k1f) : "r"(ka1));
            u32 vb0, vb1;
            u32 va0 = svb + ((u32)(((blk * 2) * 4 + tg) * 8 + g) << 2);
            u32 va1 = va0 + (32u << 2);
            asm("ld.shared.u32 %0,[%1];" : "=r"(vb0) : "r"(va0));
            asm("ld.shared.u32 %0,[%1];" : "=r"(vb1) : "r"(va1));

#pragma unroll
            for (int ti = 0; ti < 4; ti++) {
                u32 w0, w1, w2, w3;
                asm("mma.sync.aligned.m16n8k8.row.col.f16.f16.f16.f16 "
                    "{%0,%1},{%2,%3},{%4},{%5,%5};"
                    : "=r"(w0), "=r"(w1)
                    : "r"(af0[ti]), "r"(af1[ti]), "r"(k0f), "r"(0u));
                asm("mma.sync.aligned.m16n8k8.row.col.f16.f16.f16.f16 "
                    "{%0,%1},{%2,%3},{%4},{%5,%5};"
                    : "=r"(w2), "=r"(w3)
                    : "r"(af0[ti]), "r"(af1[ti]), "r"(k1f), "r"(0u));
                asm("ex2.approx.f16x2 %0,%0;" : "+r"(w0));
                asm("ex2.approx.f16x2 %0,%0;" : "+r"(w1));
                asm("ex2.approx.f16x2 %0,%0;" : "+r"(w2));
                asm("ex2.approx.f16x2 %0,%0;" : "+r"(w3));
                asm("mma.sync.aligned.m16n8k16.row.col.f32.f16.f16.f32 "
                    "{%0,%1,%2,%3},{%4,%5,%6,%7},{%8,%9},{%0,%1,%2,%3};"
                    : "+f"(o[ti][0]), "+f"(o[ti][1]), "+f"(o[ti][2]), "+f"(o[ti][3])
                    : "r"(w0), "r"(w1), "r"(w2), "r"(w3), "r"(vb0), "r"(vb1));
            }
        }

        if (pf) {
            int nb = buf ^ 1;
            s_k[nb][tid] = make_uint2(pkhf(kk.x, kk.y), pkhf(kk.z, kk.w));
            if (tid < 64) {
                int m0 = nb_base + 2 * tid, m1 = m0 + 1;
                float one0 = (m0 < M) ? 1.f : 0.f, one1 = (m1 < M) ? 1.f : 0.f;
                float dsi0 = (m0 >= L && m0 < M) ? 1.f : 0.f;
                float dsi1 = (m1 >= L && m1 < M) ? 1.f : 0.f;
                s_v[nb][2 * tid]     = make_uint4(pkhf(v0.x, v1.x), pkhf(v0.y, v1.y),
                                                  pkhf(v0.z, v1.z), pkhf(v0.w, v1.w));
                s_v[nb][2 * tid + 1] = make_uint4(pkhf(one0, one1), pkhf(dsi0, dsi1), 0u, 0u);
            }
            __syncthreads();
        }
        buf ^= 1;
    }

    // ---- epilogue: per-tile normalization + store; den/ds on tg==2 threads ----
    u32 full = 0xffffffffu;
    int src = (lane & 0x1c) | 2;
    float contrib = 0.f;
#pragma unroll
    for (int ti = 0; ti < 4; ti++) {
        float den_lo = __shfl_sync(full, o[ti][0], src);
        float den_hi = __shfl_sync(full, o[ti][2], src);
        if (tv[ti]) {
            if (tg < 2) {
                int d0 = tg * 2, d1 = tg * 2 + 1;
                float rl = 1.0f / den_lo, rh = 1.0f / den_hi;
                int qq = q0 + ti * 64;
                g_attn[qbase + (size_t)d0 * L + qq]     = o[ti][0] * rl;
                g_attn[qbase + (size_t)d1 * L + qq]     = o[ti][1] * rl;
                g_attn[qbase + (size_t)d0 * L + qq + 8] = o[ti][2] * rh;
                g_attn[qbase + (size_t)d1 * L + qq + 8] = o[ti][3] * rh;
            }
            if (tg == 2) contrib += o[ti][1] / o[ti][0] + o[ti][3] / o[ti][2];
        }
    }
#pragma unroll
    for (int off = 16; off > 0; off >>= 1) contrib += __shfl_down_sync(full, contrib, off);
    if (lane == 0) s_red[wid] = contrib;
    __syncthreads();
    if (tid == 0)
        atomicAdd(&dsout[lvl * 2 + n], (s_red[0] + s_red[1] + s_red[2] + s_red[3]) * inv_hl);
}

// ---------------- launch ----------------
extern "C" void kernel_launch(void* const* d_in, const int* in_sizes, int n_in,
                              void* d_out, int out_size) {
    const float* sp[4]; const float* iv[4]; const float* dd[4];
    for (int i = 0; i < 4; i++) {
        sp[i] = (const float*)d_in[i];
        iv[i] = (const float*)d_in[4 + i];
        dd[i] = (const float*)d_in[8 + i];
    }
    const float* Wq  = (const float*)d_in[12]; const float* bq  = (const float*)d_in[13];
    const float* Wk  = (const float*)d_in[14]; const float* bk  = (const float*)d_in[15];
    const float* Wv  = (const float*)d_in[16]; const float* bv  = (const float*)d_in[17];
    const float* Wo  = (const float*)d_in[18]; const float* bo  = (const float*)d_in[19];
    const float* Wdsk = (const float*)d_in[20]; const float* bdsk = (const float*)d_in[21];
    const float* Wdsv = (const float*)d_in[22]; const float* bdsv = (const float*)d_in[23];
    const float* gate = (const float*)d_in[24];
    float* out = (float*)d_out;

    static const int Lt[4]    = {4096, 1024, 256, 64};
    static const int qoff[4]  = {0, 2097152, 2621440, 2752512};
    static const int kvoff[4] = {0, 2113536, 2654208, 2801664};
    float* dsout = out + (out_size - 8);

    pooled_kernel<<<dim3(256, 2, 4), 256>>>(dd[0], dd[1], dd[2], dd[3], dsout);
    token_kernel<<<dim3(1024, 2, 8), 256>>>(Wdsk, bdsk, Wdsv, bdsv, gate);

    for (int lv = 0; lv < 4; lv++) {
        int L = Lt[lv], M = L + 32;
        gemm_qkv<<<dim3(L / 64, 12, 2), 128>>>(Wq + lv * 65536, Wk + lv * 65536,
                                               Wv + lv * 65536, bq + lv * 256,
                                               bk + lv * 256, bv + lv * 256,
                                               sp[lv], iv[lv], L, M, qoff[lv], kvoff[lv]);
        int gx = (L + 255) / 256;
        attn_mma<<<dim3(gx, HEADS, 2), 128>>>(qoff[lv], kvoff[lv], L, M,
                                              dsout, 1.0f / (64.0f * (float)L), lv);
    }
    for (int lv = 0; lv < 4; lv++) {
        int L = Lt[lv];
        gemm_o<<<dim3(L / 64, 4, 2), 128>>>(Wo + lv * 65536, bo + lv * 256,
                                            sp[lv], out, L, qoff[lv]);
    }
}